// round 1
// baseline (speedup 1.0000x reference)
#include <cuda_runtime.h>
#include <cuda_bf16.h>

// Problem constants (x: [64, 133, 64, 64] fp32, K=2 non-overlapping pool)
constexpr int B  = 64;
constexpr int C  = 133;
constexpr int Cm = 128;   // channels that get max-pooled
constexpr int H  = 64;
constexpr int W  = 64;
constexpr int Ho = 32;
constexpr int Wo = 32;

constexpr int NWARPS = 16;            // warps per block
constexpr int CPW    = Cm / NWARPS;   // 8 pooled channels per warp

__global__ __launch_bounds__(NWARPS * 32)
void spatial_maxpool_stats_kernel(const float* __restrict__ x,
                                  float* __restrict__ out) {
    const int b    = blockIdx.x >> 5;   // blockIdx.x = b * Ho + ho
    const int ho   = blockIdx.x & 31;
    const int lane = threadIdx.x & 31;
    const int warp = threadIdx.x >> 5;
    const int wo   = lane;              // one lane per output column

    __shared__ unsigned s_cnt[Wo];      // packed 4x8-bit argmax counts per wo
    if (threadIdx.x < Wo) s_cnt[threadIdx.x] = 0u;
    __syncthreads();

    const float* xb = x   + (size_t)b * C * H * W;
    float*       ob = out + (size_t)b * C * Ho * Wo;

    const int row_off = (2 * ho) * W + 2 * wo;

    // Warp 0 prefetches the 5 stat-channel windows (channels Cm..Cm+4)
    float s0[5], s1[5], s2[5], s3[5];
    if (warp == 0) {
#pragma unroll
        for (int j = 0; j < 5; j++) {
            const float* p  = xb + (size_t)(Cm + j) * H * W + row_off;
            float2 t = *(const float2*)p;        // row 2*ho
            float2 u = *(const float2*)(p + W);  // row 2*ho+1
            s0[j] = t.x; s1[j] = t.y; s2[j] = u.x; s3[j] = u.y;
        }
    }

    // Each warp: 8 pooled channels. Max + first-argmax per 2x2 window.
    unsigned cnt = 0;  // 4 packed 8-bit counters (per-warp partial <= 8, fits)
#pragma unroll
    for (int k = 0; k < CPW; k++) {
        const int c = warp * CPW + k;
        const float* p = xb + (size_t)c * H * W + row_off;
        float2 t = *(const float2*)p;
        float2 u = *(const float2*)(p + W);

        float m = t.x; int idx = 0;
        if (t.y > m) { m = t.y; idx = 1; }   // strict > == first-occurrence argmax
        if (u.x > m) { m = u.x; idx = 2; }
        if (u.y > m) { m = u.y; idx = 3; }

        ob[(size_t)c * Ho * Wo + ho * Wo + wo] = m;
        cnt += 1u << (idx * 8);
    }
    atomicAdd(&s_cnt[wo], cnt);
    __syncthreads();

    // Warp 0: unpack counts -> wsq, compute means / var / cov, write 5 channels
    if (warp == 0) {
        const unsigned cc = s_cnt[wo];
        const float inv = 1.0f / (float)Cm;
        const float w0 = (float)( cc        & 255u) * inv;
        const float w1 = (float)((cc >>  8) & 255u) * inv;
        const float w2 = (float)((cc >> 16) & 255u) * inv;
        const float w3 = (float)((cc >> 24) & 255u) * inv;

        // weighted means of mu channels (j = 0, 1)
        const float mean0 = s0[0]*w0 + s1[0]*w1 + s2[0]*w2 + s3[0]*w3;
        const float mean1 = s0[1]*w0 + s1[1]*w1 + s2[1]*w2 + s3[1]*w3;

        // var1 / cov1 terms (channels Cm+2, Cm+3, Cm+4 weighted by wsq)
        float var0 = s0[2]*w0 + s1[2]*w1 + s2[2]*w2 + s3[2]*w3;
        float var1 = s0[3]*w0 + s1[3]*w1 + s2[3]*w2 + s3[3]*w3;
        float cov  = s0[4]*w0 + s1[4]*w1 + s2[4]*w2 + s3[4]*w3;

        // var2 / cov2 terms: weighted central second moments of mu windows
        const float d00 = s0[0]-mean0, d10 = s1[0]-mean0, d20 = s2[0]-mean0, d30 = s3[0]-mean0;
        const float d01 = s0[1]-mean1, d11 = s1[1]-mean1, d21 = s2[1]-mean1, d31 = s3[1]-mean1;
        var0 += d00*d00*w0 + d10*d10*w1 + d20*d20*w2 + d30*d30*w3;
        var1 += d01*d01*w0 + d11*d11*w1 + d21*d21*w2 + d31*d31*w3;
        cov  += d00*d01*w0 + d10*d11*w1 + d20*d21*w2 + d30*d31*w3;

        const size_t base = (size_t)Cm * Ho * Wo + ho * Wo + wo;
        ob[base            ] = mean0;
        ob[base +     Ho*Wo] = mean1;
        ob[base + 2 * Ho*Wo] = var0;
        ob[base + 3 * Ho*Wo] = var1;
        ob[base + 4 * Ho*Wo] = cov;
    }
}

extern "C" void kernel_launch(void* const* d_in, const int* in_sizes, int n_in,
                              void* d_out, int out_size) {
    const float* x = (const float*)d_in[0];
    float* out = (float*)d_out;
    dim3 grid(B * Ho);
    dim3 block(NWARPS * 32);
    spatial_maxpool_stats_kernel<<<grid, block>>>(x, out);
}

// round 2
// speedup vs baseline: 1.0576x; 1.0576x over previous
#include <cuda_runtime.h>
#include <cuda_bf16.h>

// x: [64, 133, 64, 64] fp32 -> out [64, 133, 32, 32]
constexpr int B  = 64;
constexpr int C  = 133;
constexpr int Cm = 128;
constexpr int H  = 64;
constexpr int W  = 64;
constexpr int Ho = 32;
constexpr int Wo = 32;
constexpr int HW = H * W;

constexpr int NWARPS = 16;           // warps per block
constexpr int CPW    = Cm / NWARPS;  // 8 pooled channels per warp

__global__ __launch_bounds__(NWARPS * 32)
void spatial_maxpool_stats_kernel(const float* __restrict__ x,
                                  float* __restrict__ out) {
    const int b    = blockIdx.x >> 5;   // blockIdx.x = b*Ho + ho
    const int ho   = blockIdx.x & 31;
    const int lane = threadIdx.x & 31;
    const int warp = threadIdx.x >> 5;
    const int l16  = lane & 15;
    const bool top = lane < 16;

    __shared__ unsigned s_cnt[Wo];

    const float* xb = x   + (size_t)b * C * HW;
    float*       ob = out + (size_t)b * C * Ho * Wo;

    // One float4 per lane covers BOTH window rows for this warp's channel:
    // offset 2ho*W + 4*lane spans rows 2ho (lanes 0-15) and 2ho+1 (lanes 16-31),
    // 512B fully-coalesced per warp.
    const int loff = (2 * ho) * W + 4 * lane;
    const float* pc = xb + (size_t)(warp * CPW) * HW + loff;

    unsigned cnt0 = 0, cnt1 = 0;   // packed 4x8-bit argmax counts, windows 2*l16, 2*l16+1
    float* orow = ob + (size_t)(warp * CPW) * Ho * Wo + ho * Wo + 2 * l16;

#pragma unroll
    for (int half = 0; half < 2; half++) {
        // batch 4 independent LDG.128s
        float4 v[4];
#pragma unroll
        for (int k = 0; k < 4; k++)
            v[k] = *(const float4*)(pc + (size_t)(half * 4 + k) * HW);

        if (half == 0) {                 // overlap with load latency
            if (threadIdx.x < Wo) s_cnt[threadIdx.x] = 0u;
            __syncthreads();             // counts zeroed before any atomics below
        }

#pragma unroll
        for (int k = 0; k < 4; k++) {
            // per-half max + first-argmax (strict > = first occurrence)
            float m0 = fmaxf(v[k].x, v[k].y); int i0 = (v[k].y > v[k].x) ? 1 : 0;
            float m1 = fmaxf(v[k].z, v[k].w); int i1 = (v[k].w > v[k].z) ? 1 : 0;
            // exchange with the lane holding the other row of the same windows
            float om0 = __shfl_xor_sync(0xffffffffu, m0, 16);
            float om1 = __shfl_xor_sync(0xffffffffu, m1, 16);
            int   oi  = __shfl_xor_sync(0xffffffffu, i0 | (i1 << 1), 16);

            if (top) {
                // mine = top (positions 0/1), other = bottom (2/3); bottom wins only strictly
                float p0, p1; int j0, j1;
                if (om0 > m0) { p0 = om0; j0 = 2 + (oi & 1); } else { p0 = m0; j0 = i0; }
                if (om1 > m1) { p1 = om1; j1 = 2 + ((oi >> 1) & 1); } else { p1 = m1; j1 = i1; }
                float2 st; st.x = p0; st.y = p1;
                *(float2*)(orow + (size_t)(half * 4 + k) * Ho * Wo) = st;
                cnt0 += 1u << (8 * j0);
                cnt1 += 1u << (8 * j1);
            }
        }
    }
    if (top) {
        atomicAdd(&s_cnt[2 * l16],     cnt0);
        atomicAdd(&s_cnt[2 * l16 + 1], cnt1);
    }
    __syncthreads();

    // Warp 0: stat channels (Cm..Cm+4), lane = wo
    if (warp == 0) {
        const int wo = lane;
        const int row_off = (2 * ho) * W + 2 * wo;
        float s0[5], s1[5], s2[5], s3[5];
#pragma unroll
        for (int j = 0; j < 5; j++) {
            const float* p = xb + (size_t)(Cm + j) * HW + row_off;
            float2 t = *(const float2*)p;
            float2 u = *(const float2*)(p + W);
            s0[j] = t.x; s1[j] = t.y; s2[j] = u.x; s3[j] = u.y;
        }
        const unsigned cc = s_cnt[wo];
        const float inv = 1.0f / (float)Cm;
        const float w0 = (float)( cc        & 255u) * inv;
        const float w1 = (float)((cc >>  8) & 255u) * inv;
        const float w2 = (float)((cc >> 16) & 255u) * inv;
        const float w3 = (float)((cc >> 24) & 255u) * inv;

        const float mean0 = s0[0]*w0 + s1[0]*w1 + s2[0]*w2 + s3[0]*w3;
        const float mean1 = s0[1]*w0 + s1[1]*w1 + s2[1]*w2 + s3[1]*w3;

        float var0 = s0[2]*w0 + s1[2]*w1 + s2[2]*w2 + s3[2]*w3;
        float var1 = s0[3]*w0 + s1[3]*w1 + s2[3]*w2 + s3[3]*w3;
        float cov  = s0[4]*w0 + s1[4]*w1 + s2[4]*w2 + s3[4]*w3;

        const float d00 = s0[0]-mean0, d10 = s1[0]-mean0, d20 = s2[0]-mean0, d30 = s3[0]-mean0;
        const float d01 = s0[1]-mean1, d11 = s1[1]-mean1, d21 = s2[1]-mean1, d31 = s3[1]-mean1;
        var0 += d00*d00*w0 + d10*d10*w1 + d20*d20*w2 + d30*d30*w3;
        var1 += d01*d01*w0 + d11*d11*w1 + d21*d21*w2 + d31*d31*w3;
        cov  += d00*d01*w0 + d10*d11*w1 + d20*d21*w2 + d30*d31*w3;

        const size_t base = (size_t)Cm * Ho * Wo + ho * Wo + wo;
        ob[base            ] = mean0;
        ob[base +     Ho*Wo] = mean1;
        ob[base + 2 * Ho*Wo] = var0;
        ob[base + 3 * Ho*Wo] = var1;
        ob[base + 4 * Ho*Wo] = cov;
    }
}

extern "C" void kernel_launch(void* const* d_in, const int* in_sizes, int n_in,
                              void* d_out, int out_size) {
    const float* x = (const float*)d_in[0];
    float* out = (float*)d_out;
    spatial_maxpool_stats_kernel<<<B * Ho, NWARPS * 32>>>(x, out);
}

// round 3
// speedup vs baseline: 1.0809x; 1.0221x over previous
#include <cuda_runtime.h>
#include <cuda_bf16.h>

// x: [64, 133, 64, 64] fp32 -> out [64, 133, 32, 32]
constexpr int B  = 64;
constexpr int C  = 133;
constexpr int Cm = 128;
constexpr int H  = 64;
constexpr int W  = 64;
constexpr int Ho = 32;
constexpr int Wo = 32;
constexpr int HW = H * W;
constexpr int HoWo = Ho * Wo;

constexpr int NWARPS = 16;           // warps per block
constexpr int CPW    = Cm / NWARPS;  // 8 pooled channels per warp

__global__ __launch_bounds__(NWARPS * 32)
void spatial_maxpool_stats_kernel(const float* __restrict__ x,
                                  float* __restrict__ out) {
    const int b    = blockIdx.x >> 5;   // blockIdx.x = b*Ho + ho
    const int ho   = blockIdx.x & 31;
    const int lane = threadIdx.x & 31;
    const int warp = threadIdx.x >> 5;
    const int l16  = lane & 15;
    const int half = lane >> 4;         // which of the 2 concurrent channels

    __shared__ unsigned s_cnt[Wo];

    const float* xb = x   + (size_t)b * C * HW;
    float*       ob = out + (size_t)b * C * HoWo;

    // lane covers columns 4*l16 .. 4*l16+3 of channel (warp*CPW + 2*k + half)
    const int ch0  = warp * CPW + half;
    const float* pc = xb + (size_t)ch0 * HW + (2 * ho) * W + 4 * l16;
    float* po = ob + (size_t)ch0 * HoWo + ho * Wo + 2 * l16;

    unsigned cnt0 = 0, cnt1 = 0;  // packed 4x8-bit argmax counts for windows 2*l16, 2*l16+1

#pragma unroll
    for (int grp = 0; grp < 2; grp++) {
        // batch 4 independent LDG.128s (2 channel-iters x {top,bottom})
        float4 t[2], u[2];
#pragma unroll
        for (int k = 0; k < 2; k++) {
            const float* p = pc + (size_t)(grp * 4 + 2 * k) * HW;
            t[k] = *(const float4*)p;
            u[k] = *(const float4*)(p + W);
        }

        if (grp == 0) {                // overlap smem init with load latency
            if (threadIdx.x < Wo) s_cnt[threadIdx.x] = 0u;
            __syncthreads();           // counts zeroed before any atomics below
        }

#pragma unroll
        for (int k = 0; k < 2; k++) {
            // window a: (t.x t.y / u.x u.y), window b: (t.z t.w / u.z u.w)
            // first-occurrence argmax via strict > (later position wins only strictly)
            float mtA = fmaxf(t[k].x, t[k].y); int itA = (t[k].y > t[k].x) ? 1 : 0;
            float mbA = fmaxf(u[k].x, u[k].y); int ibA = (u[k].y > u[k].x) ? 3 : 2;
            float mA  = fmaxf(mtA, mbA);       int iA  = (mbA > mtA) ? ibA : itA;

            float mtB = fmaxf(t[k].z, t[k].w); int itB = (t[k].w > t[k].z) ? 1 : 0;
            float mbB = fmaxf(u[k].z, u[k].w); int ibB = (u[k].w > u[k].z) ? 3 : 2;
            float mB  = fmaxf(mtB, mbB);       int iB  = (mbB > mtB) ? ibB : itB;

            float2 st; st.x = mA; st.y = mB;
            *(float2*)(po + (size_t)(grp * 4 + 2 * k) * HoWo) = st;

            cnt0 += 1u << (8 * iA);
            cnt1 += 1u << (8 * iB);
        }
    }
    atomicAdd(&s_cnt[2 * l16],     cnt0);
    atomicAdd(&s_cnt[2 * l16 + 1], cnt1);
    __syncthreads();

    // Warp 0: stat channels (Cm..Cm+4), lane = wo
    if (warp == 0) {
        const int wo = lane;
        const int row_off = (2 * ho) * W + 2 * wo;
        float s0[5], s1[5], s2[5], s3[5];
#pragma unroll
        for (int j = 0; j < 5; j++) {
            const float* p = xb + (size_t)(Cm + j) * HW + row_off;
            float2 tt = *(const float2*)p;
            float2 uu = *(const float2*)(p + W);
            s0[j] = tt.x; s1[j] = tt.y; s2[j] = uu.x; s3[j] = uu.y;
        }
        const unsigned cc = s_cnt[wo];
        const float inv = 1.0f / (float)Cm;
        const float w0 = (float)( cc        & 255u) * inv;
        const float w1 = (float)((cc >>  8) & 255u) * inv;
        const float w2 = (float)((cc >> 16) & 255u) * inv;
        const float w3 = (float)((cc >> 24) & 255u) * inv;

        const float mean0 = s0[0]*w0 + s1[0]*w1 + s2[0]*w2 + s3[0]*w3;
        const float mean1 = s0[1]*w0 + s1[1]*w1 + s2[1]*w2 + s3[1]*w3;

        float var0 = s0[2]*w0 + s1[2]*w1 + s2[2]*w2 + s3[2]*w3;
        float var1 = s0[3]*w0 + s1[3]*w1 + s2[3]*w2 + s3[3]*w3;
        float cov  = s0[4]*w0 + s1[4]*w1 + s2[4]*w2 + s3[4]*w3;

        const float d00 = s0[0]-mean0, d10 = s1[0]-mean0, d20 = s2[0]-mean0, d30 = s3[0]-mean0;
        const float d01 = s0[1]-mean1, d11 = s1[1]-mean1, d21 = s2[1]-mean1, d31 = s3[1]-mean1;
        var0 += d00*d00*w0 + d10*d10*w1 + d20*d20*w2 + d30*d30*w3;
        var1 += d01*d01*w0 + d11*d11*w1 + d21*d21*w2 + d31*d31*w3;
        cov  += d00*d01*w0 + d10*d11*w1 + d20*d21*w2 + d30*d31*w3;

        const size_t base = (size_t)Cm * HoWo + ho * Wo + wo;
        ob[base           ] = mean0;
        ob[base +     HoWo] = mean1;
        ob[base + 2 * HoWo] = var0;
        ob[base + 3 * HoWo] = var1;
        ob[base + 4 * HoWo] = cov;
    }
}

extern "C" void kernel_launch(void* const* d_in, const int* in_sizes, int n_in,
                              void* d_out, int out_size) {
    const float* x = (const float*)d_in[0];
    float* out = (float*)d_out;
    spatial_maxpool_stats_kernel<<<B * Ho, NWARPS * 32>>>(x, out);
}

// round 4
// speedup vs baseline: 1.2049x; 1.1148x over previous
#include <cuda_runtime.h>
#include <cuda_bf16.h>

// x: [64, 133, 64, 64] fp32 -> out [64, 133, 32, 32]
constexpr int B  = 64;
constexpr int C  = 133;
constexpr int Cm = 128;
constexpr int H  = 64;
constexpr int W  = 64;
constexpr int Ho = 32;
constexpr int Wo = 32;
constexpr int HW = H * W;
constexpr int HoWo = Ho * Wo;

constexpr int NWARPS  = 16;
constexpr int CPW     = Cm / NWARPS;   // 8 pooled channels per warp
constexpr int NTILES  = B * Ho;        // 2048 (b, ho) tiles
constexpr int NBLOCKS = 456;           // ~3 per SM, persistent

__device__ int g_ticket;

__global__ void reset_ticket_kernel() { g_ticket = NBLOCKS; }

__global__ __launch_bounds__(NWARPS * 32, 3)
void spatial_maxpool_stats_kernel(const float* __restrict__ x,
                                  float* __restrict__ out) {
    const int lane = threadIdx.x & 31;
    const int warp = threadIdx.x >> 5;
    const int l16  = lane & 15;
    const int half = lane >> 4;

    __shared__ unsigned s_cnt[Wo];
    __shared__ float4   s_stat[2][5][32];   // [parity][stat chan][row*16 + col4]
    __shared__ int      s_next;

    int tile = blockIdx.x;
    int par  = 0;

    while (tile < NTILES) {
        const int b  = tile >> 5;
        const int ho = tile & 31;
        const float* xb = x   + (size_t)b * C * HW;
        float*       ob = out + (size_t)b * C * HoWo;

        // ---- stat-channel prefetch: warps 0-4 -> smem via cp.async (no regs held)
        if (warp < 5) {
            const float* src = xb + (size_t)(Cm + warp) * HW
                             + (2 * ho + half) * W + 4 * l16;
            unsigned dst = (unsigned)__cvta_generic_to_shared(&s_stat[par][warp][lane]);
            asm volatile("cp.async.cg.shared.global [%0], [%1], 16;\n"
                         "cp.async.commit_group;\n" :: "r"(dst), "l"(src));
        }

        // ---- pooled group 0 loads (4 x LDG.128 per thread)
        const int ch0 = warp * CPW + half;
        const float* pc = xb + (size_t)ch0 * HW + (2 * ho) * W + 4 * l16;
        float*       po = ob + (size_t)ch0 * HoWo + ho * Wo + 2 * l16;

        float4 t0[2], u0[2];
#pragma unroll
        for (int k = 0; k < 2; k++) {
            const float* p = pc + (size_t)(2 * k) * HW;
            t0[k] = *(const float4*)p;
            u0[k] = *(const float4*)(p + W);
        }

        // ---- ticket prefetch + count init (overlap with load latency)
        if (threadIdx.x == 0) s_next = atomicAdd(&g_ticket, 1);
        if (threadIdx.x < Wo) s_cnt[threadIdx.x] = 0u;
        __syncthreads();   // sync1: counts zeroed, s_next written

        // ---- pooled group 1 loads in flight while computing group 0
        float4 t1[2], u1[2];
#pragma unroll
        for (int k = 0; k < 2; k++) {
            const float* p = pc + (size_t)(4 + 2 * k) * HW;
            t1[k] = *(const float4*)p;
            u1[k] = *(const float4*)(p + W);
        }
        const int next_tile = s_next;

        unsigned cnt0 = 0, cnt1 = 0;  // packed 4x8-bit argmax counts
#pragma unroll
        for (int g = 0; g < 2; g++) {
#pragma unroll
            for (int k = 0; k < 2; k++) {
                float4 t = g ? t1[k] : t0[k];
                float4 u = g ? u1[k] : u0[k];
                // window A: (t.x t.y / u.x u.y), B: (t.z t.w / u.z u.w)
                // first-occurrence argmax: later position wins only strictly
                float mtA = fmaxf(t.x, t.y); int itA = (t.y > t.x) ? 1 : 0;
                float mbA = fmaxf(u.x, u.y); int ibA = (u.y > u.x) ? 3 : 2;
                float mA  = fmaxf(mtA, mbA); int iA  = (mbA > mtA) ? ibA : itA;

                float mtB = fmaxf(t.z, t.w); int itB = (t.w > t.z) ? 1 : 0;
                float mbB = fmaxf(u.z, u.w); int ibB = (u.w > u.z) ? 3 : 2;
                float mB  = fmaxf(mtB, mbB); int iB  = (mbB > mtB) ? ibB : itB;

                float2 st; st.x = mA; st.y = mB;
                *(float2*)(po + (size_t)(g * 4 + 2 * k) * HoWo) = st;
                cnt0 += 1u << (8 * iA);
                cnt1 += 1u << (8 * iB);
            }
        }
        atomicAdd(&s_cnt[2 * l16],     cnt0);
        atomicAdd(&s_cnt[2 * l16 + 1], cnt1);

        asm volatile("cp.async.wait_group 0;" ::: "memory");
        __syncthreads();   // sync2: counts final, stat smem ready

        // ---- epilogue: warp 0 computes the 5 stat channels from smem
        if (warp == 0) {
            const int wo = lane;
            const int e  = wo & 1;            // element pair within float4
            float s0[5], s1[5], s2[5], s3[5];
#pragma unroll
            for (int j = 0; j < 5; j++) {
                float4 r0 = s_stat[par][j][wo >> 1];        // row 2ho
                float4 r1 = s_stat[par][j][16 + (wo >> 1)]; // row 2ho+1
                s0[j] = e ? r0.z : r0.x;
                s1[j] = e ? r0.w : r0.y;
                s2[j] = e ? r1.z : r1.x;
                s3[j] = e ? r1.w : r1.y;
            }
            const unsigned cc = s_cnt[wo];
            const float inv = 1.0f / (float)Cm;
            const float w0 = (float)( cc        & 255u) * inv;
            const float w1 = (float)((cc >>  8) & 255u) * inv;
            const float w2 = (float)((cc >> 16) & 255u) * inv;
            const float w3 = (float)((cc >> 24) & 255u) * inv;

            const float mean0 = s0[0]*w0 + s1[0]*w1 + s2[0]*w2 + s3[0]*w3;
            const float mean1 = s0[1]*w0 + s1[1]*w1 + s2[1]*w2 + s3[1]*w3;

            float var0 = s0[2]*w0 + s1[2]*w1 + s2[2]*w2 + s3[2]*w3;
            float var1 = s0[3]*w0 + s1[3]*w1 + s2[3]*w2 + s3[3]*w3;
            float cov  = s0[4]*w0 + s1[4]*w1 + s2[4]*w2 + s3[4]*w3;

            const float d00 = s0[0]-mean0, d10 = s1[0]-mean0, d20 = s2[0]-mean0, d30 = s3[0]-mean0;
            const float d01 = s0[1]-mean1, d11 = s1[1]-mean1, d21 = s2[1]-mean1, d31 = s3[1]-mean1;
            var0 += d00*d00*w0 + d10*d10*w1 + d20*d20*w2 + d30*d30*w3;
            var1 += d01*d01*w0 + d11*d11*w1 + d21*d21*w2 + d31*d31*w3;
            cov  += d00*d01*w0 + d10*d11*w1 + d20*d21*w2 + d30*d31*w3;

            const size_t base = (size_t)Cm * HoWo + ho * Wo + wo;
            ob[base           ] = mean0;
            ob[base +     HoWo] = mean1;
            ob[base + 2 * HoWo] = var0;
            ob[base + 3 * HoWo] = var1;
            ob[base + 4 * HoWo] = cov;
        }

        tile = next_tile;
        par ^= 1;
    }
}

extern "C" void kernel_launch(void* const* d_in, const int* in_sizes, int n_in,
                              void* d_out, int out_size) {
    const float* x = (const float*)d_in[0];
    float* out = (float*)d_out;
    reset_ticket_kernel<<<1, 1>>>();
    spatial_maxpool_stats_kernel<<<NBLOCKS, NWARPS * 32>>>(x, out);
}

// round 5
// speedup vs baseline: 1.2062x; 1.0010x over previous
#include <cuda_runtime.h>
#include <cuda_bf16.h>

// x: [64, 133, 64, 64] fp32 -> out [64, 133, 32, 32]
constexpr int B  = 64;
constexpr int C  = 133;
constexpr int Cm = 128;
constexpr int H  = 64;
constexpr int W  = 64;
constexpr int Ho = 32;
constexpr int Wo = 32;
constexpr int HW = H * W;
constexpr int HoWo = Ho * Wo;

constexpr int NWARPS  = 16;
constexpr int CPW     = Cm / NWARPS;   // 8 pooled channels per warp
constexpr int NTILES  = B * Ho;        // 2048 (b, ho) tiles
constexpr int NBLOCKS = 456;           // 3 per SM, persistent
constexpr unsigned BARCNT = NWARPS * 32;  // 512

__global__ __launch_bounds__(NWARPS * 32, 3)
void spatial_maxpool_stats_kernel(const float* __restrict__ x,
                                  float* __restrict__ out) {
    const int lane = threadIdx.x & 31;
    const int warp = threadIdx.x >> 5;
    const int l16  = lane & 15;
    const int half = lane >> 4;

    __shared__ unsigned s_cnt[2][Wo];        // parity double-buffered counts
    __shared__ float4   s_stat[2][5][32];    // [parity][stat chan][row*16 + col4]

    if (threadIdx.x < 64) s_cnt[threadIdx.x >> 5][threadIdx.x & 31] = 0u;
    __syncthreads();   // both count buffers start zeroed ("free")

    int iter = 0;
    for (int tile = blockIdx.x; tile < NTILES; tile += NBLOCKS, iter++) {
        const int par = iter & 1;
        const int bar_ready = 1 + par;   // workers arrive, warp0 syncs
        const int bar_free  = 3 + par;   // warp0 arrives, workers sync

        const int b  = tile >> 5;
        const int ho = tile & 31;
        const float* xb = x   + (size_t)b * C * HW;
        float*       ob = out + (size_t)b * C * HoWo;

        const int ch0 = warp * CPW + half;
        const float* pc = xb + (size_t)ch0 * HW + (2 * ho) * W + 4 * l16;
        float*       po = ob + (size_t)ch0 * HoWo + ho * Wo + 2 * l16;

        // ---- pooled group 0 loads start immediately (registers only)
        float4 t0[2], u0[2];
#pragma unroll
        for (int k = 0; k < 2; k++) {
            const float* p = pc + (size_t)(2 * k) * HW;
            t0[k] = *(const float4*)p;
            u0[k] = *(const float4*)(p + W);
        }

        // ---- workers gate on "buffer par free" (warp0 freed it 2 tiles ago)
        if (warp != 0 && iter >= 2)
            asm volatile("bar.sync %0, %1;" :: "r"(bar_free), "r"(BARCNT) : "memory");

        // ---- stat-channel prefetch: warps 0-4 -> smem via cp.async
        if (warp < 5) {
            const float* src = xb + (size_t)(Cm + warp) * HW
                             + (2 * ho + half) * W + 4 * l16;
            unsigned dst = (unsigned)__cvta_generic_to_shared(&s_stat[par][warp][lane]);
            asm volatile("cp.async.cg.shared.global [%0], [%1], 16;\n"
                         "cp.async.commit_group;\n" :: "r"(dst), "l"(src));
        }

        // ---- pooled group 1 loads
        float4 t1[2], u1[2];
#pragma unroll
        for (int k = 0; k < 2; k++) {
            const float* p = pc + (size_t)(4 + 2 * k) * HW;
            t1[k] = *(const float4*)p;
            u1[k] = *(const float4*)(p + W);
        }

        unsigned cnt0 = 0, cnt1 = 0;  // packed 4x8-bit argmax counts
#pragma unroll
        for (int g = 0; g < 2; g++) {
#pragma unroll
            for (int k = 0; k < 2; k++) {
                float4 t = g ? t1[k] : t0[k];
                float4 u = g ? u1[k] : u0[k];
                // window A: (t.x t.y / u.x u.y), B: (t.z t.w / u.z u.w)
                // first-occurrence argmax: later position wins only strictly
                float mtA = fmaxf(t.x, t.y); int itA = (t.y > t.x) ? 1 : 0;
                float mbA = fmaxf(u.x, u.y); int ibA = (u.y > u.x) ? 3 : 2;
                float mA  = fmaxf(mtA, mbA); int iA  = (mbA > mtA) ? ibA : itA;

                float mtB = fmaxf(t.z, t.w); int itB = (t.w > t.z) ? 1 : 0;
                float mbB = fmaxf(u.z, u.w); int ibB = (u.w > u.z) ? 3 : 2;
                float mB  = fmaxf(mtB, mbB); int iB  = (mbB > mtB) ? ibB : itB;

                float2 st; st.x = mA; st.y = mB;
                *(float2*)(po + (size_t)(g * 4 + 2 * k) * HoWo) = st;
                cnt0 += 1u << (8 * iA);
                cnt1 += 1u << (8 * iB);
            }
        }
        atomicAdd(&s_cnt[par][2 * l16],     cnt0);
        atomicAdd(&s_cnt[par][2 * l16 + 1], cnt1);

        // cp.async issued this tile must complete before signaling ready
        asm volatile("cp.async.wait_group 0;" ::: "memory");

        if (warp != 0) {
            // signal counts + stats ready; do NOT block — roll into next tile
            asm volatile("bar.arrive %0, %1;" :: "r"(bar_ready), "r"(BARCNT) : "memory");
        } else {
            // warp0: wait for all workers, then compute the 5 stat channels
            asm volatile("bar.sync %0, %1;" :: "r"(bar_ready), "r"(BARCNT) : "memory");

            const int wo = lane;
            const unsigned cc = s_cnt[par][wo];
            s_cnt[par][wo] = 0u;                // re-zero for reuse in 2 tiles

            const int e = wo & 1;
            float s0[5], s1[5], s2[5], s3[5];
#pragma unroll
            for (int j = 0; j < 5; j++) {
                float4 r0 = s_stat[par][j][wo >> 1];        // row 2ho
                float4 r1 = s_stat[par][j][16 + (wo >> 1)]; // row 2ho+1
                s0[j] = e ? r0.z : r0.x;
                s1[j] = e ? r0.w : r0.y;
                s2[j] = e ? r1.z : r1.x;
                s3[j] = e ? r1.w : r1.y;
            }
            const float inv = 1.0f / (float)Cm;
            const float w0 = (float)( cc        & 255u) * inv;
            const float w1 = (float)((cc >>  8) & 255u) * inv;
            const float w2 = (float)((cc >> 16) & 255u) * inv;
            const float w3 = (float)((cc >> 24) & 255u) * inv;

            const float mean0 = s0[0]*w0 + s1[0]*w1 + s2[0]*w2 + s3[0]*w3;
            const float mean1 = s0[1]*w0 + s1[1]*w1 + s2[1]*w2 + s3[1]*w3;

            float var0 = s0[2]*w0 + s1[2]*w1 + s2[2]*w2 + s3[2]*w3;
            float var1 = s0[3]*w0 + s1[3]*w1 + s2[3]*w2 + s3[3]*w3;
            float cov  = s0[4]*w0 + s1[4]*w1 + s2[4]*w2 + s3[4]*w3;

            const float d00 = s0[0]-mean0, d10 = s1[0]-mean0, d20 = s2[0]-mean0, d30 = s3[0]-mean0;
            const float d01 = s0[1]-mean1, d11 = s1[1]-mean1, d21 = s2[1]-mean1, d31 = s3[1]-mean1;
            var0 += d00*d00*w0 + d10*d10*w1 + d20*d20*w2 + d30*d30*w3;
            var1 += d01*d01*w0 + d11*d11*w1 + d21*d21*w2 + d31*d31*w3;
            cov  += d00*d01*w0 + d10*d11*w1 + d20*d21*w2 + d30*d31*w3;

            const size_t base = (size_t)Cm * HoWo + ho * Wo + wo;
            ob[base           ] = mean0;
            ob[base +     HoWo] = mean1;
            ob[base + 2 * HoWo] = var0;
            ob[base + 3 * HoWo] = var1;
            ob[base + 4 * HoWo] = cov;

            // buffer par (counts + stats) is now reusable
            asm volatile("bar.arrive %0, %1;" :: "r"(bar_free), "r"(BARCNT) : "memory");
        }
    }
}

extern "C" void kernel_launch(void* const* d_in, const int* in_sizes, int n_in,
                              void* d_out, int out_size) {
    const float* x = (const float*)d_in[0];
    float* out = (float*)d_out;
    spatial_maxpool_stats_kernel<<<NBLOCKS, NWARPS * 32>>>(x, out);
}